// round 1
// baseline (speedup 1.0000x reference)
#include <cuda_runtime.h>

// Scratch scalars (no allocations allowed — use __device__ globals)
__device__ float g_ssrc_i;   // dot(h[i], W1)
__device__ float g_sdst_j;   // dot(h[j], W2)
__device__ float g_sum;      // sum of leaky_relu over matching edges

__device__ __forceinline__ float leaky(float v) {
    return v >= 0.f ? v : 0.2f * v;
}

// Kernel 1: compute s_src[i], s_dst[j], zero accumulator. One block of 128.
__global__ void gat_scalars(const float* __restrict__ h,
                            const float* __restrict__ W,
                            const int* __restrict__ ip,
                            const int* __restrict__ jp,
                            int D) {
    int t = threadIdx.x;
    int i = ip[0];
    int j = jp[0];
    float a = 0.f, c = 0.f;
    for (int k = t; k < D; k += blockDim.x) {
        a += h[(size_t)i * D + k] * W[k];       // W1 = W[0:D]
        c += h[(size_t)j * D + k] * W[D + k];   // W2 = W[D:2D]
    }
    // warp reduce
    #pragma unroll
    for (int off = 16; off > 0; off >>= 1) {
        a += __shfl_down_sync(0xffffffffu, a, off);
        c += __shfl_down_sync(0xffffffffu, c, off);
    }
    __shared__ float sa[32], sc[32];
    int w = t >> 5;
    if ((t & 31) == 0) { sa[w] = a; sc[w] = c; }
    __syncthreads();
    if (t == 0) {
        int nw = (blockDim.x + 31) >> 5;
        float ta = 0.f, tc = 0.f;
        for (int k = 0; k < nw; k++) { ta += sa[k]; tc += sc[k]; }
        g_ssrc_i = ta;
        g_sdst_j = tc;
        g_sum = 0.f;
    }
}

// Per-match contribution: serial D-dim dot with W2, leaky-relu, atomic add.
// Only ~E/N (~32) threads across the whole grid ever take this path.
__device__ __forceinline__ void contribute(int dst,
                                           const float* __restrict__ h,
                                           const float* __restrict__ W,
                                           float bval, int D) {
    const float4* __restrict__ hr = (const float4*)(h + (size_t)dst * D);
    const float4* __restrict__ w2 = (const float4*)(W + D);
    float sd = 0.f;
    int n4 = D >> 2;
    #pragma unroll 8
    for (int k = 0; k < n4; k++) {
        float4 hv = hr[k];
        float4 wv = w2[k];
        sd += hv.x * wv.x + hv.y * wv.y + hv.z * wv.z + hv.w * wv.w;
    }
    float v = leaky(g_ssrc_i + sd + bval);
    atomicAdd(&g_sum, v);
}

// Kernel 2: scan edges. Each thread loads one int4 = 2 edges (16B coalesced).
__global__ void gat_edges(const int4* __restrict__ g4,
                          long long nPairs, int rem,
                          const int2* __restrict__ gall,
                          const float* __restrict__ h,
                          const float* __restrict__ W,
                          const float* __restrict__ bptr,
                          const int* __restrict__ ip,
                          int D) {
    long long idx = (long long)blockIdx.x * blockDim.x + threadIdx.x;
    int i = ip[0];
    if (idx < nPairs) {
        int4 p = g4[idx];
        if (p.x == i) contribute(p.y, h, W, bptr[0], D);
        if (p.z == i) contribute(p.w, h, W, bptr[0], D);
    } else if (rem && idx == nPairs) {
        int2 p = gall[2 * nPairs];  // the last (odd) edge
        if (p.x == i) contribute(p.y, h, W, bptr[0], D);
    }
}

// Kernel 3: final scalar.
__global__ void gat_finish(float* __restrict__ out,
                           const float* __restrict__ bptr) {
    float e = leaky(g_ssrc_i + g_sdst_j + bptr[0]);
    out[0] = e / g_sum;
}

extern "C" void kernel_launch(void* const* d_in, const int* in_sizes, int n_in,
                              void* d_out, int out_size) {
    // metadata order: g (E*2 int32), h (N*D f32), i (int), j (int), W (2D f32), b (1 f32)
    const int*   g = (const int*)d_in[0];
    const float* h = (const float*)d_in[1];
    const int*   ip = (const int*)d_in[2];
    const int*   jp = (const int*)d_in[3];
    const float* W = (const float*)d_in[4];
    const float* b = (const float*)d_in[5];
    float* out = (float*)d_out;

    long long E = (long long)in_sizes[0] / 2;
    int D = in_sizes[4] / 2;

    long long nPairs = E / 2;
    int rem = (int)(E & 1);

    gat_scalars<<<1, 128>>>(h, W, ip, jp, D);

    long long nThreads = nPairs + (rem ? 1 : 0);
    int block = 256;
    long long nBlocks = (nThreads + block - 1) / block;
    gat_edges<<<(unsigned)nBlocks, block>>>((const int4*)g, nPairs, rem,
                                            (const int2*)g, h, W, b, ip, D);

    gat_finish<<<1, 1>>>(out, b);
}